// round 1
// baseline (speedup 1.0000x reference)
#include <cuda_runtime.h>

#define NN 8192
#define FF 64
#define OO 64

// Scratch (device globals: allocation-free per harness rules)
__device__ float g_Y[NN * OO];    // features @ W2^T  (W cols 64..127)
__device__ float g_XW1[NN * OO];  // features @ W1^T  (W cols 0..63)

// ---------------------------------------------------------------------------
// Kernel 1: per-row dual projection. One block per row, 128 threads:
// thread j<64  -> XW1[i][j]  = sum_f x[i][f] * W[j][f]
// thread j>=64 -> Y[i][j-64] = sum_f x[i][f] * W[j-64][64+f]
// ---------------------------------------------------------------------------
__global__ __launch_bounds__(128) void proj_kernel(const float* __restrict__ x,
                                                   const float* __restrict__ W) {
    __shared__ float xs[FF];
    int i = blockIdx.x;
    int t = threadIdx.x;            // 0..127
    if (t < FF) xs[t] = x[i * FF + t];
    __syncthreads();

    int o    = t & 63;
    int half = t >> 6;              // 0 -> W1 part, 1 -> W2 part
    const float* wrow = W + o * (2 * FF) + half * FF;

    float acc = 0.0f;
#pragma unroll
    for (int f = 0; f < FF; ++f) acc = fmaf(xs[f], wrow[f], acc);

    if (half == 0) g_XW1[i * OO + o] = acc;
    else           g_Y[i * OO + o]   = acc;
}

// ---------------------------------------------------------------------------
// Kernel 2: T = A @ Y with fused rowsum(A); epilogue:
//   out[i][j] = XW1[i][j] + T[i][j] / (deg[i] + 1)
// BM=64 rows per block, BN=64 (all outputs), BK=32, 256 threads, 4x4 microtile.
// ---------------------------------------------------------------------------
#define BM 64
#define BK 32

__global__ __launch_bounds__(256) void sage_main_kernel(const float* __restrict__ A,
                                                        float* __restrict__ out) {
    __shared__ float As[BK][BM + 4];   // transposed A tile, row = 68 floats (16B-aligned rows)
    __shared__ float Bs[BK][OO];       // Y tile

    const int tid = threadIdx.x;
    const int tx  = tid & 15;          // output col group: cols tx*4..tx*4+3
    const int ty  = tid >> 4;          // output row group: rows ty*4..ty*4+3
    const int i0  = blockIdx.x * BM;

    float acc[4][4] = {};
    float dpart[4]  = {0.f, 0.f, 0.f, 0.f};

    const int lr  = tid >> 3;          // A-load: 0..31
    const int lc4 = (tid & 7) * 4;     // A-load col: 0,4,..,28
    const int br  = tid >> 4;          // B-load: 0..15
    const int bc4 = (tid & 15) * 4;    // B-load col

    for (int k0 = 0; k0 < NN; k0 += BK) {
        // Load A tile (64 x 32), store transposed into As[k][row]
#pragma unroll
        for (int p = 0; p < 2; ++p) {
            int row = lr + p * 32;
            float4 v = *reinterpret_cast<const float4*>(
                &A[(size_t)(i0 + row) * NN + k0 + lc4]);
            As[lc4 + 0][row] = v.x;
            As[lc4 + 1][row] = v.y;
            As[lc4 + 2][row] = v.z;
            As[lc4 + 3][row] = v.w;
        }
        // Load Y tile (32 x 64) row-major
#pragma unroll
        for (int p = 0; p < 2; ++p) {
            int row = br + p * 16;
            float4 v = *reinterpret_cast<const float4*>(&g_Y[(size_t)(k0 + row) * OO + bc4]);
            *reinterpret_cast<float4*>(&Bs[row][bc4]) = v;
        }
        __syncthreads();

        // Fused deg partials: this thread covers in-tile k = {2*tx, 2*tx+1}
        // for its 4 rows (reduced across the 16 tx lanes at the end).
#pragma unroll
        for (int m = 0; m < 4; ++m)
            dpart[m] += As[2 * tx][ty * 4 + m] + As[2 * tx + 1][ty * 4 + m];

#pragma unroll
        for (int k = 0; k < BK; ++k) {
            float4 a = *reinterpret_cast<const float4*>(&As[k][ty * 4]);
            float4 b = *reinterpret_cast<const float4*>(&Bs[k][tx * 4]);
            float av[4] = {a.x, a.y, a.z, a.w};
            float bv[4] = {b.x, b.y, b.z, b.w};
#pragma unroll
            for (int m = 0; m < 4; ++m)
#pragma unroll
                for (int n = 0; n < 4; ++n)
                    acc[m][n] = fmaf(av[m], bv[n], acc[m][n]);
        }
        __syncthreads();
    }

    // Reduce deg partials across the 16 tx lanes (xor offsets < 16 stay
    // within the same ty half-warp: lane = (ty&1)*16 + tx).
#pragma unroll
    for (int off = 1; off < 16; off <<= 1)
#pragma unroll
        for (int m = 0; m < 4; ++m)
            dpart[m] += __shfl_xor_sync(0xFFFFFFFFu, dpart[m], off);

    // Epilogue: out = XW1 + acc / (deg + 1)
#pragma unroll
    for (int m = 0; m < 4; ++m) {
        float inv = 1.0f / (dpart[m] + 1.0f);
        int gi = i0 + ty * 4 + m;
#pragma unroll
        for (int n = 0; n < 4; ++n) {
            int gj = tx * 4 + n;
            out[(size_t)gi * OO + gj] = g_XW1[(size_t)gi * OO + gj] + acc[m][n] * inv;
        }
    }
}

extern "C" void kernel_launch(void* const* d_in, const int* in_sizes, int n_in,
                              void* d_out, int out_size) {
    const float* adj      = (const float*)d_in[0];  // [8192, 8192]
    const float* features = (const float*)d_in[1];  // [8192, 64]
    const float* W        = (const float*)d_in[2];  // [64, 128]
    float* out            = (float*)d_out;          // [8192, 64]

    proj_kernel<<<NN, 128>>>(features, W);
    sage_main_kernel<<<NN / BM, 256>>>(adj, out);
}

// round 4
// speedup vs baseline: 1.8784x; 1.8784x over previous
#include <cuda_runtime.h>
#include <cstdint>

#define NN 8192
#define FF 64
#define OO 64
#define NB 72                 // 64 Y cols + 1 ones col (deg) + 7 zero pad
#define BM 64
#define BK 32
#define NTILES (NN / BK)      // 256
#define STAGES 3

// smem: per stage A[64][36] + B[72][36] floats (pad 4 -> conflict-free frags)
#define APAD 36
#define A_BYTES (BM * APAD * 4)          // 9216
#define B_BYTES (NB * APAD * 4)          // 10368
#define STAGE_BYTES (A_BYTES + B_BYTES)  // 19584
#define SMEM_TOTAL (STAGES * STAGE_BYTES)

// -------------------- scratch --------------------
__device__ float g_YT[NB * NN];   // YT[n][k]: n<64 -> (X@W2^T)[k][n]; n=64 -> 1; n>64 -> 0
__device__ float g_XW1[NN * OO];  // X @ W1^T

__device__ __forceinline__ uint32_t smem_u32(const void* p) {
    uint32_t a;
    asm("{ .reg .u64 t; cvta.to.shared.u64 t, %1; cvt.u32.u64 %0, t; }" : "=r"(a) : "l"(p));
    return a;
}
__device__ __forceinline__ void cpasync16(uint32_t dst, const float* src) {
    asm volatile("cp.async.cg.shared.global [%0], [%1], 16;\n" :: "r"(dst), "l"(src));
}
__device__ __forceinline__ void mma_tf32(float* c, uint32_t a0, uint32_t a1, uint32_t a2,
                                         uint32_t a3, uint32_t b0, uint32_t b1) {
    asm volatile(
        "mma.sync.aligned.m16n8k8.row.col.f32.tf32.tf32.f32 "
        "{%0,%1,%2,%3}, {%4,%5,%6,%7}, {%8,%9}, {%0,%1,%2,%3};\n"
        : "+f"(c[0]), "+f"(c[1]), "+f"(c[2]), "+f"(c[3])
        : "r"(a0), "r"(a1), "r"(a2), "r"(a3), "r"(b0), "r"(b1));
}

// -------------------- kernel 1: projections (+ YT pad rows) --------------------
__global__ __launch_bounds__(128) void proj_kernel(const float* __restrict__ x,
                                                   const float* __restrict__ W) {
    __shared__ float xs[FF];
    int i = blockIdx.x;
    int t = threadIdx.x;
    if (t < FF) xs[t] = x[i * FF + t];
    if (t < 8) g_YT[(size_t)(64 + t) * NN + i] = (t == 0) ? 1.0f : 0.0f;
    __syncthreads();

    int o = t & 63;
    int half = t >> 6;
    const float* wrow = W + o * (2 * FF) + half * FF;
    float acc = 0.0f;
#pragma unroll
    for (int f = 0; f < FF; ++f) acc = fmaf(xs[f], wrow[f], acc);

    if (half == 0) g_XW1[(size_t)i * OO + o] = acc;
    else           g_YT[(size_t)o * NN + i]  = acc;
}

// -------------------- kernel 2: fused A@Yext (tf32 mma.sync) + epilogue --------
__device__ __forceinline__ void load_stage(uint32_t sbase, int stage, int k0,
                                           const float* __restrict__ Abase, int tid) {
    uint32_t sA = sbase + stage * STAGE_BYTES;
    uint32_t sB = sA + A_BYTES;
    // A tile: 64 rows x 8 float4
#pragma unroll
    for (int i = 0; i < 4; ++i) {
        int idx = tid + i * 128;            // 0..511
        int r = idx >> 3, c = idx & 7;
        cpasync16(sA + r * (APAD * 4) + c * 16, Abase + (size_t)r * NN + k0 + c * 4);
    }
    // B tile: 72 rows x 8 float4 = 576
#pragma unroll
    for (int i = 0; i < 5; ++i) {
        int idx = tid + i * 128;
        if (idx < NB * 8) {
            int r = idx >> 3, c = idx & 7;
            cpasync16(sB + r * (APAD * 4) + c * 16, g_YT + (size_t)r * NN + k0 + c * 4);
        }
    }
    asm volatile("cp.async.commit_group;\n" ::: "memory");
}

__global__ __launch_bounds__(128, 1) void sage_mma_kernel(const float* __restrict__ A,
                                                          float* __restrict__ out) {
    extern __shared__ char smem[];
    const uint32_t sbase = smem_u32(smem);
    const int tid = threadIdx.x;
    const int wid = tid >> 5;
    const int lane = tid & 31;
    const int grp = lane >> 2;       // 0..7
    const int kq  = lane & 3;        // 0..3
    const int m0  = wid * 16;        // warp's row stripe within BM

    const float* Abase = A + (size_t)blockIdx.x * BM * NN;

    float acc[9][4];
#pragma unroll
    for (int t = 0; t < 9; ++t)
#pragma unroll
        for (int r = 0; r < 4; ++r) acc[t][r] = 0.0f;

    load_stage(sbase, 0, 0, Abase, tid);
    load_stage(sbase, 1, BK, Abase, tid);

    for (int i = 0; i < NTILES; ++i) {
        if (i + 1 < NTILES) asm volatile("cp.async.wait_group 1;\n" ::: "memory");
        else                asm volatile("cp.async.wait_group 0;\n" ::: "memory");
        __syncthreads();

        if (i + 2 < NTILES) load_stage(sbase, (i + 2) % STAGES, (i + 2) * BK, Abase, tid);

        const uint32_t* As = (const uint32_t*)(smem + (size_t)(i % STAGES) * STAGE_BYTES);
        const uint32_t* Bs = As + BM * APAD;

#pragma unroll
        for (int ks = 0; ks < BK; ks += 8) {
            uint32_t a0 = As[(m0 + grp)     * APAD + ks + kq];
            uint32_t a1 = As[(m0 + grp + 8) * APAD + ks + kq];
            uint32_t a2 = As[(m0 + grp)     * APAD + ks + 4 + kq];
            uint32_t a3 = As[(m0 + grp + 8) * APAD + ks + 4 + kq];
#pragma unroll
            for (int t = 0; t < 9; ++t) {
                uint32_t b0 = Bs[(t * 8 + grp) * APAD + ks + kq];
                uint32_t b1 = Bs[(t * 8 + grp) * APAD + ks + 4 + kq];
                mma_tf32(acc[t], a0, a1, a2, a3, b0, b1);
            }
        }
    }

    // deg: accumulator column 64 = n-tile 8, col-in-tile 0 (held by kq==0 lanes)
    float deg_lo = __shfl_sync(0xFFFFFFFFu, acc[8][0], lane & ~3);
    float deg_hi = __shfl_sync(0xFFFFFFFFu, acc[8][2], lane & ~3);
    float inv_lo = 1.0f / (deg_lo + 1.0f);
    float inv_hi = 1.0f / (deg_hi + 1.0f);

    int row_lo = blockIdx.x * BM + m0 + grp;
    int row_hi = row_lo + 8;
#pragma unroll
    for (int t = 0; t < 8; ++t) {
        int col = t * 8 + 2 * kq;
        const float2 x_lo = *(const float2*)&g_XW1[(size_t)row_lo * OO + col];
        const float2 x_hi = *(const float2*)&g_XW1[(size_t)row_hi * OO + col];
        float2 o_lo = make_float2(x_lo.x + acc[t][0] * inv_lo, x_lo.y + acc[t][1] * inv_lo);
        float2 o_hi = make_float2(x_hi.x + acc[t][2] * inv_hi, x_hi.y + acc[t][3] * inv_hi);
        *(float2*)&out[(size_t)row_lo * OO + col] = o_lo;
        *(float2*)&out[(size_t)row_hi * OO + col] = o_hi;
    }
}

// -------------------- launch --------------------
extern "C" void kernel_launch(void* const* d_in, const int* in_sizes, int n_in,
                              void* d_out, int out_size) {
    const float* adj      = (const float*)d_in[0];  // [8192, 8192]
    const float* features = (const float*)d_in[1];  // [8192, 64]
    const float* W        = (const float*)d_in[2];  // [64, 128]
    float* out            = (float*)d_out;          // [8192, 64]

    cudaFuncSetAttribute(sage_mma_kernel,
                         cudaFuncAttributeMaxDynamicSharedMemorySize, SMEM_TOTAL);

    proj_kernel<<<NN, 128>>>(features, W);
    sage_mma_kernel<<<NN / BM, 128, SMEM_TOTAL>>>(adj, out);
}

// round 5
// speedup vs baseline: 2.9808x; 1.5869x over previous
#include <cuda_runtime.h>
#include <cstdint>

#define NN 8192
#define FF 64
#define OO 64
#define NB 80                 // 64 Y cols + 1 ones col (deg) + 15 zero pad (10 n-tiles)
#define BM 64
#define BK 32
#define NTILES (NN / BK)      // 256
#define STAGES 4

#define APAD 36
#define A_BYTES (BM * APAD * 4)          // 9216
#define B_BYTES (NB * APAD * 4)          // 11520
#define STAGE_BYTES (A_BYTES + B_BYTES)  // 20736
#define SMEM_MAIN (STAGES * STAGE_BYTES) // 82944

// -------------------- scratch --------------------
__device__ float g_YT[NB * NN];   // YT[n][k]: n<64 -> (X@W2^T)[k][n]; n=64 -> 1; n>64 -> 0
__device__ float g_XW1[NN * OO];  // X @ W1^T

__device__ __forceinline__ uint32_t smem_u32(const void* p) {
    uint32_t a;
    asm("{ .reg .u64 t; cvta.to.shared.u64 t, %1; cvt.u32.u64 %0, t; }" : "=r"(a) : "l"(p));
    return a;
}
__device__ __forceinline__ void cpasync16(uint32_t dst, const float* src) {
    asm volatile("cp.async.cg.shared.global [%0], [%1], 16;\n" :: "r"(dst), "l"(src));
}
__device__ __forceinline__ void mma_tf32(float* c, uint32_t a0, uint32_t a1, uint32_t a2,
                                         uint32_t a3, uint32_t b0, uint32_t b1) {
    asm volatile(
        "mma.sync.aligned.m16n8k8.row.col.f32.tf32.tf32.f32 "
        "{%0,%1,%2,%3}, {%4,%5,%6,%7}, {%8,%9}, {%0,%1,%2,%3};\n"
        : "+f"(c[0]), "+f"(c[1]), "+f"(c[2]), "+f"(c[3])
        : "r"(a0), "r"(a1), "r"(a2), "r"(a3), "r"(b0), "r"(b1));
}

// ===================== kernel 1: projections =====================
// Grid 256 x 256 threads. Block handles 32 rows of X.
// Computes XW1[i][0:64] and Y[i][0:64] (stored transposed into g_YT).
// smem floats: Wst[64][136] | xst[64][34] | ys[32][66]
#define WST_STRIDE 136
#define XST_STRIDE 34
#define YS_STRIDE  66
#define PROJ_SMEM ((64 * WST_STRIDE + 64 * XST_STRIDE + 32 * YS_STRIDE) * 4)

__global__ __launch_bounds__(256) void proj_kernel(const float* __restrict__ x,
                                                   const float* __restrict__ W) {
    extern __shared__ float s[];
    float* Wst = s;                          // Wst[k][n] = W[n&63][(n>>6)*64 + k]
    float* xst = Wst + 64 * WST_STRIDE;      // xst[k][r] = x[i0+r][k]
    float* ys  = xst + 64 * XST_STRIDE;      // ys[r][q]  = Y[i0+r][q]

    const int t  = threadIdx.x;
    const int i0 = blockIdx.x * 32;

    // Load W (coalesced), scatter into Wst
#pragma unroll
    for (int j = 0; j < 32; ++j) {
        int idx = t + j * 256;               // 0..8191
        int o = idx >> 7, c = idx & 127;
        Wst[(c & 63) * WST_STRIDE + (c >> 6) * 64 + o] = W[idx];
    }
    // Load x rows (coalesced), scatter transposed
#pragma unroll
    for (int j = 0; j < 8; ++j) {
        int idx = t + j * 256;               // 0..2047
        int r = idx >> 6, k = idx & 63;
        xst[k * XST_STRIDE + r] = x[(size_t)(i0 + r) * FF + k];
    }
    // YT pad rows 64..79 for this block's column range
#pragma unroll
    for (int j = 0; j < 2; ++j) {
        int idx = t + j * 256;               // 0..511
        int p = idx >> 5, r = idx & 31;
        g_YT[(size_t)(64 + p) * NN + i0 + r] = (p == 0) ? 1.0f : 0.0f;
    }
    __syncthreads();

    const int tx = t & 15;                   // col group: outputs tx*8 .. tx*8+7
    const int ty = t >> 4;                   // row pair: rows 2*ty, 2*ty+1

    float acc[2][8];
#pragma unroll
    for (int r = 0; r < 2; ++r)
#pragma unroll
        for (int j = 0; j < 8; ++j) acc[r][j] = 0.0f;

#pragma unroll
    for (int k = 0; k < 64; ++k) {
        float2 a  = *(const float2*)&xst[k * XST_STRIDE + 2 * ty];
        float4 b0 = *(const float4*)&Wst[k * WST_STRIDE + tx * 8];
        float4 b1 = *(const float4*)&Wst[k * WST_STRIDE + tx * 8 + 4];
        float av[2] = {a.x, a.y};
        float bv[8] = {b0.x, b0.y, b0.z, b0.w, b1.x, b1.y, b1.z, b1.w};
#pragma unroll
        for (int r = 0; r < 2; ++r)
#pragma unroll
            for (int j = 0; j < 8; ++j) acc[r][j] = fmaf(av[r], bv[j], acc[r][j]);
    }

    if (tx < 8) {
        // XW1 half: direct coalesced float4 stores
#pragma unroll
        for (int r = 0; r < 2; ++r) {
            size_t base = (size_t)(i0 + 2 * ty + r) * OO + tx * 8;
            *(float4*)&g_XW1[base]     = make_float4(acc[r][0], acc[r][1], acc[r][2], acc[r][3]);
            *(float4*)&g_XW1[base + 4] = make_float4(acc[r][4], acc[r][5], acc[r][6], acc[r][7]);
        }
    } else {
        // Y half: stage into smem for transposed coalesced write
        int qb = (tx - 8) * 8;
#pragma unroll
        for (int r = 0; r < 2; ++r)
#pragma unroll
            for (int j = 0; j < 8; ++j)
                ys[(2 * ty + r) * YS_STRIDE + qb + j] = acc[r][j];
    }
    __syncthreads();

    // Write YT: col = t&63, rows rb..rb+7
    {
        int col = t & 63, rb = (t >> 6) * 8;
        float v[8];
#pragma unroll
        for (int j = 0; j < 8; ++j) v[j] = ys[(rb + j) * YS_STRIDE + col];
        size_t base = (size_t)col * NN + i0 + rb;
        *(float4*)&g_YT[base]     = make_float4(v[0], v[1], v[2], v[3]);
        *(float4*)&g_YT[base + 4] = make_float4(v[4], v[5], v[6], v[7]);
    }
}

// ===================== kernel 2: fused A@Yext + epilogue =====================
__device__ __forceinline__ void load_stage(uint32_t sbase, int stage, int k0,
                                           const float* __restrict__ Abase, int tid) {
    uint32_t sA = sbase + stage * STAGE_BYTES;
    uint32_t sB = sA + A_BYTES;
    // A tile: 64 rows x 8 float4 = 512 tasks
#pragma unroll
    for (int i = 0; i < 2; ++i) {
        int idx = tid + i * 256;
        int r = idx >> 3, c = idx & 7;
        cpasync16(sA + r * (APAD * 4) + c * 16, Abase + (size_t)r * NN + k0 + c * 4);
    }
    // B tile: 80 rows x 8 float4 = 640 tasks
#pragma unroll
    for (int i = 0; i < 3; ++i) {
        int idx = tid + i * 256;
        if (idx < NB * 8) {
            int r = idx >> 3, c = idx & 7;
            cpasync16(sB + r * (APAD * 4) + c * 16, g_YT + (size_t)r * NN + k0 + c * 4);
        }
    }
    asm volatile("cp.async.commit_group;\n" ::: "memory");
}

__global__ __launch_bounds__(256, 1) void sage_mma_kernel(const float* __restrict__ A,
                                                          float* __restrict__ out) {
    extern __shared__ char smem[];
    const uint32_t sbase = smem_u32(smem);
    const int tid   = threadIdx.x;
    const int wid   = tid >> 5;
    const int lane  = tid & 31;
    const int grp   = lane >> 2;        // 0..7
    const int kq    = lane & 3;         // 0..3
    const int m0    = (wid & 3) * 16;   // m-stripe within BM
    const int nhalf = wid >> 2;         // 0: tiles 0-4, 1: tiles 5-9
    const int tbase = nhalf * 5;

    const float* Abase = A + (size_t)blockIdx.x * BM * NN;

    float acc[5][4];
#pragma unroll
    for (int t = 0; t < 5; ++t)
#pragma unroll
        for (int r = 0; r < 4; ++r) acc[t][r] = 0.0f;

    load_stage(sbase, 0, 0, Abase, tid);
    load_stage(sbase, 1, BK, Abase, tid);
    load_stage(sbase, 2, 2 * BK, Abase, tid);

    for (int i = 0; i < NTILES; ++i) {
        asm volatile("cp.async.wait_group 2;\n" ::: "memory");
        __syncthreads();

        if (i + 3 < NTILES) load_stage(sbase, (i + 3) & 3, (i + 3) * BK, Abase, tid);
        else                asm volatile("cp.async.commit_group;\n" ::: "memory");

        const uint32_t* As = (const uint32_t*)(smem + (size_t)(i & 3) * STAGE_BYTES);
        const uint32_t* Bs = As + BM * APAD;

#pragma unroll
        for (int ks = 0; ks < BK; ks += 8) {
            uint32_t a0 = As[(m0 + grp)     * APAD + ks + kq];
            uint32_t a1 = As[(m0 + grp + 8) * APAD + ks + kq];
            uint32_t a2 = As[(m0 + grp)     * APAD + ks + 4 + kq];
            uint32_t a3 = As[(m0 + grp + 8) * APAD + ks + 4 + kq];
#pragma unroll
            for (int lt = 0; lt < 5; ++lt) {
                int gt = tbase + lt;
                uint32_t b0 = Bs[(gt * 8 + grp) * APAD + ks + kq];
                uint32_t b1 = Bs[(gt * 8 + grp) * APAD + ks + 4 + kq];
                mma_tf32(acc[lt], a0, a1, a2, a3, b0, b1);
            }
        }
    }

    __syncthreads();                       // all mma smem reads done
    float* degbuf = (float*)smem;          // reuse stage memory

    // deg = column 64 = global tile 8 (nhalf1 local tile 3), col-in-tile 0, kq==0
    if (nhalf == 1 && kq == 0) {
        degbuf[m0 + grp]     = acc[3][0];
        degbuf[m0 + grp + 8] = acc[3][2];
    }
    __syncthreads();

    int row_lo = blockIdx.x * BM + m0 + grp;
    int row_hi = row_lo + 8;
    float inv_lo = 1.0f / (degbuf[m0 + grp]     + 1.0f);
    float inv_hi = 1.0f / (degbuf[m0 + grp + 8] + 1.0f);

#pragma unroll
    for (int lt = 0; lt < 5; ++lt) {
        int gt = tbase + lt;
        if (gt < 8) {                      // only cols 0..63 are real outputs
            int col = gt * 8 + 2 * kq;
            const float2 x_lo = *(const float2*)&g_XW1[(size_t)row_lo * OO + col];
            const float2 x_hi = *(const float2*)&g_XW1[(size_t)row_hi * OO + col];
            float2 o_lo = make_float2(x_lo.x + acc[lt][0] * inv_lo,
                                      x_lo.y + acc[lt][1] * inv_lo);
            float2 o_hi = make_float2(x_hi.x + acc[lt][2] * inv_hi,
                                      x_hi.y + acc[lt][3] * inv_hi);
            *(float2*)&out[(size_t)row_lo * OO + col] = o_lo;
            *(float2*)&out[(size_t)row_hi * OO + col] = o_hi;
        }
    }
}

// -------------------- launch --------------------
extern "C" void kernel_launch(void* const* d_in, const int* in_sizes, int n_in,
                              void* d_out, int out_size) {
    const float* adj      = (const float*)d_in[0];  // [8192, 8192]
    const float* features = (const float*)d_in[1];  // [8192, 64]
    const float* W        = (const float*)d_in[2];  // [64, 128]
    float* out            = (float*)d_out;          // [8192, 64]

    cudaFuncSetAttribute(proj_kernel,
                         cudaFuncAttributeMaxDynamicSharedMemorySize, PROJ_SMEM);
    cudaFuncSetAttribute(sage_mma_kernel,
                         cudaFuncAttributeMaxDynamicSharedMemorySize, SMEM_MAIN);

    proj_kernel<<<NN / 32, 256, PROJ_SMEM>>>(features, W);
    sage_mma_kernel<<<NN / BM, 256, SMEM_MAIN>>>(adj, out);
}

// round 6
// speedup vs baseline: 5.6427x; 1.8930x over previous
#include <cuda_runtime.h>
#include <cstdint>

#define NN 8192
#define FF 64
#define OO 64
#define NB 72                 // 64 Y cols + 1 ones col (deg) + 7 zero pad (9 n-tiles)
#define BM 64
#define BK 32
#define KHALF 4096
#define NTILES (KHALF / BK)   // 128
#define STAGES 4

#define APAD 36
#define A_BYTES (BM * APAD * 4)          // 9216
#define B_BYTES (NB * APAD * 4)          // 10368
#define STAGE_BYTES (A_BYTES + B_BYTES)  // 19584
#define SMEM_MAIN (STAGES * STAGE_BYTES) // 78336 -> 2 CTAs/SM

// -------------------- scratch --------------------
__device__ float g_YT[NB * NN];    // YT[n][k]: n<64 -> (X@W2^T)[k][n]; n=64 -> 1; n>64 -> 0
__device__ float g_XW1[NN * OO];   // X @ W1^T
__device__ float g_T[2][NN * NB];  // split-K partials of A @ YT^T (col 64 = deg partial)

__device__ __forceinline__ uint32_t smem_u32(const void* p) {
    uint32_t a;
    asm("{ .reg .u64 t; cvta.to.shared.u64 t, %1; cvt.u32.u64 %0, t; }" : "=r"(a) : "l"(p));
    return a;
}
__device__ __forceinline__ void cpasync16(uint32_t dst, const float* src) {
    asm volatile("cp.async.cg.shared.global [%0], [%1], 16;\n" :: "r"(dst), "l"(src));
}
__device__ __forceinline__ void mma_tf32(float* c, uint32_t a0, uint32_t a1, uint32_t a2,
                                         uint32_t a3, uint32_t b0, uint32_t b1) {
    asm volatile(
        "mma.sync.aligned.m16n8k8.row.col.f32.tf32.tf32.f32 "
        "{%0,%1,%2,%3}, {%4,%5,%6,%7}, {%8,%9}, {%0,%1,%2,%3};\n"
        : "+f"(c[0]), "+f"(c[1]), "+f"(c[2]), "+f"(c[3])
        : "r"(a0), "r"(a1), "r"(a2), "r"(a3), "r"(b0), "r"(b1));
}

// ===================== kernel 1: projections =====================
#define WST_STRIDE 136
#define XST_STRIDE 34
#define YS_STRIDE  66
#define PROJ_SMEM ((64 * WST_STRIDE + 64 * XST_STRIDE + 32 * YS_STRIDE) * 4)

__global__ __launch_bounds__(256) void proj_kernel(const float* __restrict__ x,
                                                   const float* __restrict__ W) {
    extern __shared__ float s[];
    float* Wst = s;                          // Wst[k][n] = W[n&63][(n>>6)*64 + k]
    float* xst = Wst + 64 * WST_STRIDE;      // xst[k][r] = x[i0+r][k]
    float* ys  = xst + 64 * XST_STRIDE;      // ys[r][q]  = Y[i0+r][q]

    const int t  = threadIdx.x;
    const int i0 = blockIdx.x * 32;

#pragma unroll
    for (int j = 0; j < 32; ++j) {
        int idx = t + j * 256;               // 0..8191
        int o = idx >> 7, c = idx & 127;
        Wst[(c & 63) * WST_STRIDE + (c >> 6) * 64 + o] = W[idx];
    }
#pragma unroll
    for (int j = 0; j < 8; ++j) {
        int idx = t + j * 256;               // 0..2047
        int r = idx >> 6, k = idx & 63;
        xst[k * XST_STRIDE + r] = x[(size_t)(i0 + r) * FF + k];
    }
    // YT pad rows 64..71 for this block's column range
    {
        int p = t >> 5, r = t & 31;
        if (p < 8) g_YT[(size_t)(64 + p) * NN + i0 + r] = (p == 0) ? 1.0f : 0.0f;
    }
    __syncthreads();

    const int tx = t & 15;
    const int ty = t >> 4;

    float acc[2][8];
#pragma unroll
    for (int r = 0; r < 2; ++r)
#pragma unroll
        for (int j = 0; j < 8; ++j) acc[r][j] = 0.0f;

#pragma unroll
    for (int k = 0; k < 64; ++k) {
        float2 a  = *(const float2*)&xst[k * XST_STRIDE + 2 * ty];
        float4 b0 = *(const float4*)&Wst[k * WST_STRIDE + tx * 8];
        float4 b1 = *(const float4*)&Wst[k * WST_STRIDE + tx * 8 + 4];
        float av[2] = {a.x, a.y};
        float bv[8] = {b0.x, b0.y, b0.z, b0.w, b1.x, b1.y, b1.z, b1.w};
#pragma unroll
        for (int r = 0; r < 2; ++r)
#pragma unroll
            for (int j = 0; j < 8; ++j) acc[r][j] = fmaf(av[r], bv[j], acc[r][j]);
    }

    if (tx < 8) {
#pragma unroll
        for (int r = 0; r < 2; ++r) {
            size_t base = (size_t)(i0 + 2 * ty + r) * OO + tx * 8;
            *(float4*)&g_XW1[base]     = make_float4(acc[r][0], acc[r][1], acc[r][2], acc[r][3]);
            *(float4*)&g_XW1[base + 4] = make_float4(acc[r][4], acc[r][5], acc[r][6], acc[r][7]);
        }
    } else {
        int qb = (tx - 8) * 8;
#pragma unroll
        for (int r = 0; r < 2; ++r)
#pragma unroll
            for (int j = 0; j < 8; ++j)
                ys[(2 * ty + r) * YS_STRIDE + qb + j] = acc[r][j];
    }
    __syncthreads();

    {
        int col = t & 63, rb = (t >> 6) * 8;
        float v[8];
#pragma unroll
        for (int j = 0; j < 8; ++j) v[j] = ys[(rb + j) * YS_STRIDE + col];
        size_t base = (size_t)col * NN + i0 + rb;
        *(float4*)&g_YT[base]     = make_float4(v[0], v[1], v[2], v[3]);
        *(float4*)&g_YT[base + 4] = make_float4(v[4], v[5], v[6], v[7]);
    }
}

// ===================== kernel 2: split-K A@Yext (tf32 mma.sync) =====================
__device__ __forceinline__ void load_stage(uint32_t sbase, int stage, int k0,
                                           const float* __restrict__ Abase,
                                           const float* __restrict__ Bbase, int tid) {
    uint32_t sA = sbase + stage * STAGE_BYTES;
    uint32_t sB = sA + A_BYTES;
    // A tile: 64 rows x 8 float4 = 512 tasks
#pragma unroll
    for (int i = 0; i < 4; ++i) {
        int idx = tid + i * 128;
        int r = idx >> 3, c = idx & 7;
        cpasync16(sA + r * (APAD * 4) + c * 16, Abase + (size_t)r * NN + k0 + c * 4);
    }
    // B tile: 72 rows x 8 float4 = 576 tasks
#pragma unroll
    for (int i = 0; i < 5; ++i) {
        int idx = tid + i * 128;
        if (idx < NB * 8) {
            int r = idx >> 3, c = idx & 7;
            cpasync16(sB + r * (APAD * 4) + c * 16, Bbase + (size_t)r * NN + k0 + c * 4);
        }
    }
    asm volatile("cp.async.commit_group;\n" ::: "memory");
}

__global__ __launch_bounds__(128, 2) void sage_mma_kernel(const float* __restrict__ A) {
    extern __shared__ char smem[];
    const uint32_t sbase = smem_u32(smem);
    const int tid  = threadIdx.x;
    const int wid  = tid >> 5;
    const int lane = tid & 31;
    const int grp  = lane >> 2;       // 0..7
    const int kq   = lane & 3;        // 0..3
    const int m0   = wid * 16;

    const int mtile = blockIdx.x >> 1;
    const int kh    = blockIdx.x & 1;
    const float* Abase = A + (size_t)mtile * BM * NN + (size_t)kh * KHALF;
    const float* Bbase = g_YT + (size_t)kh * KHALF;

    float acc[9][4];
#pragma unroll
    for (int t = 0; t < 9; ++t)
#pragma unroll
        for (int r = 0; r < 4; ++r) acc[t][r] = 0.0f;

    load_stage(sbase, 0, 0, Abase, Bbase, tid);
    load_stage(sbase, 1, BK, Abase, Bbase, tid);
    load_stage(sbase, 2, 2 * BK, Abase, Bbase, tid);

    for (int i = 0; i < NTILES; ++i) {
        asm volatile("cp.async.wait_group 2;\n" ::: "memory");
        __syncthreads();

        if (i + 3 < NTILES) load_stage(sbase, (i + 3) & 3, (i + 3) * BK, Abase, Bbase, tid);
        else                asm volatile("cp.async.commit_group;\n" ::: "memory");

        const uint32_t* As = (const uint32_t*)(smem + (size_t)(i & 3) * STAGE_BYTES);
        const uint32_t* Bs = As + BM * APAD;

#pragma unroll
        for (int ks = 0; ks < BK; ks += 8) {
            uint32_t a0 = As[(m0 + grp)     * APAD + ks + kq];
            uint32_t a1 = As[(m0 + grp + 8) * APAD + ks + kq];
            uint32_t a2 = As[(m0 + grp)     * APAD + ks + 4 + kq];
            uint32_t a3 = As[(m0 + grp + 8) * APAD + ks + 4 + kq];
#pragma unroll
            for (int t = 0; t < 9; ++t) {
                uint32_t b0 = Bs[(t * 8 + grp) * APAD + ks + kq];
                uint32_t b1 = Bs[(t * 8 + grp) * APAD + ks + 4 + kq];
                mma_tf32(acc[t], a0, a1, a2, a3, b0, b1);
            }
        }
    }

    // Store raw partials (72 cols incl. deg col 64)
    int row_lo = mtile * BM + m0 + grp;
    int row_hi = row_lo + 8;
    float* dst = g_T[kh];
#pragma unroll
    for (int t = 0; t < 9; ++t) {
        int col = t * 8 + 2 * kq;
        *(float2*)&dst[(size_t)row_lo * NB + col] = make_float2(acc[t][0], acc[t][1]);
        *(float2*)&dst[(size_t)row_hi * NB + col] = make_float2(acc[t][2], acc[t][3]);
    }
}

// ===================== kernel 3: combine + epilogue =====================
__global__ __launch_bounds__(256) void epilogue_kernel(float* __restrict__ out) {
    int idx = blockIdx.x * blockDim.x + threadIdx.x;   // r*64 + c
    int r = idx >> 6;
    int c = idx & 63;
    float deg = g_T[0][(size_t)r * NB + 64] + g_T[1][(size_t)r * NB + 64] + 1.0f;
    float t   = g_T[0][(size_t)r * NB + c]  + g_T[1][(size_t)r * NB + c];
    out[idx] = g_XW1[idx] + t / deg;
}

// -------------------- launch --------------------
extern "C" void kernel_launch(void* const* d_in, const int* in_sizes, int n_in,
                              void* d_out, int out_size) {
    const float* adj      = (const float*)d_in[0];  // [8192, 8192]
    const float* features = (const float*)d_in[1];  // [8192, 64]
    const float* W        = (const float*)d_in[2];  // [64, 128]
    float* out            = (float*)d_out;          // [8192, 64]

    cudaFuncSetAttribute(proj_kernel,
                         cudaFuncAttributeMaxDynamicSharedMemorySize, PROJ_SMEM);
    cudaFuncSetAttribute(sage_mma_kernel,
                         cudaFuncAttributeMaxDynamicSharedMemorySize, SMEM_MAIN);

    proj_kernel<<<NN / 32, 256, PROJ_SMEM>>>(features, W);
    sage_mma_kernel<<<2 * (NN / BM), 128, SMEM_MAIN>>>(adj);
    epilogue_kernel<<<(NN * OO) / 256, 256>>>(out);
}

// round 7
// speedup vs baseline: 6.6974x; 1.1869x over previous
#include <cuda_runtime.h>
#include <cstdint>

#define NN 8192
#define FF 64
#define OO 64
#define NB 72                 // 64 Y cols + 1 ones col (deg) + 7 zero pad (9 n-tiles)
#define BM 128
#define BK 32
#define SPLITK 4
#define KHALF (NN / SPLITK)   // 2048
#define NTILES (KHALF / BK)   // 64
#define STAGES 3

#define APAD 36
#define A_BYTES (BM * APAD * 4)          // 18432
#define B_BYTES (NB * APAD * 4)          // 10368
#define STAGE_BYTES (A_BYTES + B_BYTES)  // 28800
#define SMEM_MAIN (STAGES * STAGE_BYTES) // 86400 -> 2 CTAs/SM

// -------------------- scratch --------------------
__device__ float g_YT[NB * NN];        // YT[n][k]: n<64 -> (X@W2^T)[k][n]; n=64 -> 1; else 0
__device__ float g_XW1[NN * OO];       // X @ W1^T
__device__ float g_T[SPLITK][NN * NB]; // split-K partials (col 64 = deg partial)

__device__ __forceinline__ uint32_t smem_u32(const void* p) {
    uint32_t a;
    asm("{ .reg .u64 t; cvta.to.shared.u64 t, %1; cvt.u32.u64 %0, t; }" : "=r"(a) : "l"(p));
    return a;
}
__device__ __forceinline__ void cpasync16(uint32_t dst, const float* src) {
    asm volatile("cp.async.cg.shared.global [%0], [%1], 16;\n" :: "r"(dst), "l"(src));
}
__device__ __forceinline__ void mma_tf32(float* c, uint32_t a0, uint32_t a1, uint32_t a2,
                                         uint32_t a3, uint32_t b0, uint32_t b1) {
    asm volatile(
        "mma.sync.aligned.m16n8k8.row.col.f32.tf32.tf32.f32 "
        "{%0,%1,%2,%3}, {%4,%5,%6,%7}, {%8,%9}, {%0,%1,%2,%3};\n"
        : "+f"(c[0]), "+f"(c[1]), "+f"(c[2]), "+f"(c[3])
        : "r"(a0), "r"(a1), "r"(a2), "r"(a3), "r"(b0), "r"(b1));
}

// ===================== kernel 1: projections =====================
#define WST_STRIDE 136
#define XST_STRIDE 34
#define YS_STRIDE  66
#define PROJ_SMEM ((64 * WST_STRIDE + 64 * XST_STRIDE + 32 * YS_STRIDE) * 4)

__global__ __launch_bounds__(256) void proj_kernel(const float* __restrict__ x,
                                                   const float* __restrict__ W) {
    extern __shared__ float s[];
    float* Wst = s;                          // Wst[k][n] = W[n&63][(n>>6)*64 + k]
    float* xst = Wst + 64 * WST_STRIDE;      // xst[k][r] = x[i0+r][k]
    float* ys  = xst + 64 * XST_STRIDE;      // ys[r][q]  = Y[i0+r][q]

    const int t  = threadIdx.x;
    const int i0 = blockIdx.x * 32;

#pragma unroll
    for (int j = 0; j < 32; ++j) {
        int idx = t + j * 256;               // 0..8191
        int o = idx >> 7, c = idx & 127;
        Wst[(c & 63) * WST_STRIDE + (c >> 6) * 64 + o] = W[idx];
    }
#pragma unroll
    for (int j = 0; j < 8; ++j) {
        int idx = t + j * 256;               // 0..2047
        int r = idx >> 6, k = idx & 63;
        xst[k * XST_STRIDE + r] = x[(size_t)(i0 + r) * FF + k];
    }
    {
        int p = t >> 5, r = t & 31;
        if (p < 8) g_YT[(size_t)(64 + p) * NN + i0 + r] = (p == 0) ? 1.0f : 0.0f;
    }
    __syncthreads();

    const int tx = t & 15;
    const int ty = t >> 4;

    float acc[2][8];
#pragma unroll
    for (int r = 0; r < 2; ++r)
#pragma unroll
        for (int j = 0; j < 8; ++j) acc[r][j] = 0.0f;

#pragma unroll
    for (int k = 0; k < 64; ++k) {
        float2 a  = *(const float2*)&xst[k * XST_STRIDE + 2 * ty];
        float4 b0 = *(const float4*)&Wst[k * WST_STRIDE + tx * 8];
        float4 b1 = *(const float4*)&Wst[k * WST_STRIDE + tx * 8 + 4];
        float av[2] = {a.x, a.y};
        float bv[8] = {b0.x, b0.y, b0.z, b0.w, b1.x, b1.y, b1.z, b1.w};
#pragma unroll
        for (int r = 0; r < 2; ++r)
#pragma unroll
            for (int j = 0; j < 8; ++j) acc[r][j] = fmaf(av[r], bv[j], acc[r][j]);
    }

    if (tx < 8) {
#pragma unroll
        for (int r = 0; r < 2; ++r) {
            size_t base = (size_t)(i0 + 2 * ty + r) * OO + tx * 8;
            *(float4*)&g_XW1[base]     = make_float4(acc[r][0], acc[r][1], acc[r][2], acc[r][3]);
            *(float4*)&g_XW1[base + 4] = make_float4(acc[r][4], acc[r][5], acc[r][6], acc[r][7]);
        }
    } else {
        int qb = (tx - 8) * 8;
#pragma unroll
        for (int r = 0; r < 2; ++r)
#pragma unroll
            for (int j = 0; j < 8; ++j)
                ys[(2 * ty + r) * YS_STRIDE + qb + j] = acc[r][j];
    }
    __syncthreads();

    {
        int col = t & 63, rb = (t >> 6) * 8;
        float v[8];
#pragma unroll
        for (int j = 0; j < 8; ++j) v[j] = ys[(rb + j) * YS_STRIDE + col];
        size_t base = (size_t)col * NN + i0 + rb;
        *(float4*)&g_YT[base]     = make_float4(v[0], v[1], v[2], v[3]);
        *(float4*)&g_YT[base + 4] = make_float4(v[4], v[5], v[6], v[7]);
    }
}

// ===================== kernel 2: split-K A@Yext, warp-m32 =====================
__device__ __forceinline__ void load_stage(uint32_t sbase, int stage, int k0,
                                           const float* __restrict__ Abase,
                                           const float* __restrict__ Bbase, int tid) {
    uint32_t sA = sbase + stage * STAGE_BYTES;
    uint32_t sB = sA + A_BYTES;
    // A tile: 128 rows x 8 float4 = 1024 tasks
#pragma unroll
    for (int i = 0; i < 8; ++i) {
        int idx = tid + i * 128;
        int r = idx >> 3, c = idx & 7;
        cpasync16(sA + r * (APAD * 4) + c * 16, Abase + (size_t)r * NN + k0 + c * 4);
    }
    // B tile: 72 rows x 8 float4 = 576 tasks
#pragma unroll
    for (int i = 0; i < 5; ++i) {
        int idx = tid + i * 128;
        if (idx < NB * 8) {
            int r = idx >> 3, c = idx & 7;
            cpasync16(sB + r * (APAD * 4) + c * 16, Bbase + (size_t)r * NN + k0 + c * 4);
        }
    }
    asm volatile("cp.async.commit_group;\n" ::: "memory");
}

__global__ __launch_bounds__(128, 2) void sage_mma_kernel(const float* __restrict__ A) {
    extern __shared__ char smem[];
    const uint32_t sbase = smem_u32(smem);
    const int tid  = threadIdx.x;
    const int wid  = tid >> 5;
    const int lane = tid & 31;
    const int grp  = lane >> 2;       // 0..7
    const int kq   = lane & 3;        // 0..3
    const int m0   = wid * 32;        // warp covers rows m0..m0+31 (two m16 tiles)

    const int mtile = blockIdx.x >> 2;       // 0..63
    const int kh    = blockIdx.x & 3;        // 0..3
    const float* Abase = A + (size_t)mtile * BM * NN + (size_t)kh * KHALF;
    const float* Bbase = g_YT + (size_t)kh * KHALF;

    float acc[2][9][4];
#pragma unroll
    for (int h = 0; h < 2; ++h)
#pragma unroll
        for (int t = 0; t < 9; ++t)
#pragma unroll
            for (int r = 0; r < 4; ++r) acc[h][t][r] = 0.0f;

    load_stage(sbase, 0, 0, Abase, Bbase, tid);
    load_stage(sbase, 1, BK, Abase, Bbase, tid);

    for (int i = 0; i < NTILES; ++i) {
        asm volatile("cp.async.wait_group 1;\n" ::: "memory");
        __syncthreads();

        if (i + 2 < NTILES) load_stage(sbase, (i + 2) % STAGES, (i + 2) * BK, Abase, Bbase, tid);
        else                asm volatile("cp.async.commit_group;\n" ::: "memory");

        const uint32_t* As = (const uint32_t*)(smem + (size_t)(i % STAGES) * STAGE_BYTES);
        const uint32_t* Bs = As + BM * APAD;

#pragma unroll
        for (int ks = 0; ks < BK; ks += 8) {
            // two m16 tiles worth of A frags
            uint32_t a0[2], a1[2], a2[2], a3[2];
#pragma unroll
            for (int h = 0; h < 2; ++h) {
                int rb = m0 + h * 16;
                a0[h] = As[(rb + grp)     * APAD + ks + kq];
                a1[h] = As[(rb + grp + 8) * APAD + ks + kq];
                a2[h] = As[(rb + grp)     * APAD + ks + 4 + kq];
                a3[h] = As[(rb + grp + 8) * APAD + ks + 4 + kq];
            }
#pragma unroll
            for (int t = 0; t < 9; ++t) {
                uint32_t b0 = Bs[(t * 8 + grp) * APAD + ks + kq];
                uint32_t b1 = Bs[(t * 8 + grp) * APAD + ks + 4 + kq];
                mma_tf32(acc[0][t], a0[0], a1[0], a2[0], a3[0], b0, b1);
                mma_tf32(acc[1][t], a0[1], a1[1], a2[1], a3[1], b0, b1);
            }
        }
    }

    // Store raw partials (72 cols incl. deg col 64)
    float* dst = g_T[kh];
#pragma unroll
    for (int h = 0; h < 2; ++h) {
        int row_lo = mtile * BM + m0 + h * 16 + grp;
        int row_hi = row_lo + 8;
#pragma unroll
        for (int t = 0; t < 9; ++t) {
            int col = t * 8 + 2 * kq;
            *(float2*)&dst[(size_t)row_lo * NB + col] = make_float2(acc[h][t][0], acc[h][t][1]);
            *(float2*)&dst[(size_t)row_hi * NB + col] = make_float2(acc[h][t][2], acc[h][t][3]);
        }
    }
}

// ===================== kernel 3: combine + epilogue =====================
__global__ __launch_bounds__(256) void epilogue_kernel(float* __restrict__ out) {
    int idx = blockIdx.x * blockDim.x + threadIdx.x;   // r*64 + c
    int r = idx >> 6;
    int c = idx & 63;
    float deg = 1.0f, t = 0.0f;
#pragma unroll
    for (int s = 0; s < SPLITK; ++s) {
        deg += g_T[s][(size_t)r * NB + 64];
        t   += g_T[s][(size_t)r * NB + c];
    }
    out[idx] = g_XW1[idx] + t / deg;
}

// -------------------- launch --------------------
extern "C" void kernel_launch(void* const* d_in, const int* in_sizes, int n_in,
                              void* d_out, int out_size) {
    const float* adj      = (const float*)d_in[0];  // [8192, 8192]
    const float* features = (const float*)d_in[1];  // [8192, 64]
    const float* W        = (const float*)d_in[2];  // [64, 128]
    float* out            = (float*)d_out;          // [8192, 64]

    cudaFuncSetAttribute(proj_kernel,
                         cudaFuncAttributeMaxDynamicSharedMemorySize, PROJ_SMEM);
    cudaFuncSetAttribute(sage_mma_kernel,
                         cudaFuncAttributeMaxDynamicSharedMemorySize, SMEM_MAIN);

    proj_kernel<<<NN / 32, 256, PROJ_SMEM>>>(features, W);
    sage_mma_kernel<<<SPLITK * (NN / BM), 128, SMEM_MAIN>>>(adj);
    epilogue_kernel<<<(NN * OO) / 256, 256>>>(out);
}

// round 8
// speedup vs baseline: 7.6489x; 1.1421x over previous
#include <cuda_runtime.h>
#include <cstdint>

#define NN 8192
#define FF 64
#define OO 64
#define NB 64                  // B cols (Y only; deg handled separately)
#define BM 128
#define BK2 32                 // k per tile
#define SPLITK 4
#define KHALF (NN / SPLITK)    // 2048
#define NT (KHALF / BK2)       // 64 tiles per CTA

#define AW 20                  // 32-bit words per smem row (16 data bf16x2 + 4 pad)
#define A_WORDS (BM * AW)      // 2560
#define B_WORDS (NB * AW)      // 1280
#define STG_WORDS (A_WORDS + B_WORDS)   // 3840 words = 15360 B
#define SMEM_MAIN (3 * STG_WORDS * 4)   // 46080 B -> 2 CTAs/SM easily

// -------------------- scratch --------------------
__device__ float g_YT[NB * NN];          // YT[n][k] = (X @ W2^T)[k][n]
__device__ float g_XW1[NN * OO];         // X @ W1^T
__device__ float g_T[SPLITK][NN * OO];   // split-K partials of A @ YT^T
__device__ float g_degp[SPLITK][NN];     // split-K partials of rowsum(A)

__device__ __forceinline__ void mma_bf16(float* c, uint32_t a0, uint32_t a1, uint32_t a2,
                                         uint32_t a3, uint32_t b0, uint32_t b1) {
    asm volatile(
        "mma.sync.aligned.m16n8k16.row.col.f32.bf16.bf16.f32 "
        "{%0,%1,%2,%3}, {%4,%5,%6,%7}, {%8,%9}, {%0,%1,%2,%3};\n"
        : "+f"(c[0]), "+f"(c[1]), "+f"(c[2]), "+f"(c[3])
        : "r"(a0), "r"(a1), "r"(a2), "r"(a3), "r"(b0), "r"(b1));
}
#define CVT2(d, hi, lo) \
    asm("cvt.rn.bf16x2.f32 %0, %1, %2;" : "=r"(d) : "f"(hi), "f"(lo))

// ===================== kernel 1: projections (unchanged core) =====================
#define WST_STRIDE 136
#define XST_STRIDE 34
#define YS_STRIDE  66
#define PROJ_SMEM ((64 * WST_STRIDE + 64 * XST_STRIDE + 32 * YS_STRIDE) * 4)

__global__ __launch_bounds__(256) void proj_kernel(const float* __restrict__ x,
                                                   const float* __restrict__ W) {
    extern __shared__ float s[];
    float* Wst = s;                          // Wst[k][n] = W[n&63][(n>>6)*64 + k]
    float* xst = Wst + 64 * WST_STRIDE;      // xst[k][r] = x[i0+r][k]
    float* ys  = xst + 64 * XST_STRIDE;      // ys[r][q]  = Y[i0+r][q]

    const int t  = threadIdx.x;
    const int i0 = blockIdx.x * 32;

#pragma unroll
    for (int j = 0; j < 32; ++j) {
        int idx = t + j * 256;
        int o = idx >> 7, c = idx & 127;
        Wst[(c & 63) * WST_STRIDE + (c >> 6) * 64 + o] = W[idx];
    }
#pragma unroll
    for (int j = 0; j < 8; ++j) {
        int idx = t + j * 256;
        int r = idx >> 6, k = idx & 63;
        xst[k * XST_STRIDE + r] = x[(size_t)(i0 + r) * FF + k];
    }
    __syncthreads();

    const int tx = t & 15;
    const int ty = t >> 4;

    float acc[2][8];
#pragma unroll
    for (int r = 0; r < 2; ++r)
#pragma unroll
        for (int j = 0; j < 8; ++j) acc[r][j] = 0.0f;

#pragma unroll
    for (int k = 0; k < 64; ++k) {
        float2 a  = *(const float2*)&xst[k * XST_STRIDE + 2 * ty];
        float4 b0 = *(const float4*)&Wst[k * WST_STRIDE + tx * 8];
        float4 b1 = *(const float4*)&Wst[k * WST_STRIDE + tx * 8 + 4];
        float av[2] = {a.x, a.y};
        float bv[8] = {b0.x, b0.y, b0.z, b0.w, b1.x, b1.y, b1.z, b1.w};
#pragma unroll
        for (int r = 0; r < 2; ++r)
#pragma unroll
            for (int j = 0; j < 8; ++j) acc[r][j] = fmaf(av[r], bv[j], acc[r][j]);
    }

    if (tx < 8) {
#pragma unroll
        for (int r = 0; r < 2; ++r) {
            size_t base = (size_t)(i0 + 2 * ty + r) * OO + tx * 8;
            *(float4*)&g_XW1[base]     = make_float4(acc[r][0], acc[r][1], acc[r][2], acc[r][3]);
            *(float4*)&g_XW1[base + 4] = make_float4(acc[r][4], acc[r][5], acc[r][6], acc[r][7]);
        }
    } else {
        int qb = (tx - 8) * 8;
#pragma unroll
        for (int r = 0; r < 2; ++r)
#pragma unroll
            for (int j = 0; j < 8; ++j)
                ys[(2 * ty + r) * YS_STRIDE + qb + j] = acc[r][j];
    }
    __syncthreads();

    {
        int col = t & 63, rb = (t >> 6) * 8;
        float v[8];
#pragma unroll
        for (int j = 0; j < 8; ++j) v[j] = ys[(rb + j) * YS_STRIDE + col];
        size_t base = (size_t)col * NN + i0 + rb;
        *(float4*)&g_YT[base]     = make_float4(v[0], v[1], v[2], v[3]);
        *(float4*)&g_YT[base + 4] = make_float4(v[4], v[5], v[6], v[7]);
    }
}

// ===================== kernel 2: split-K A@Y, bf16 smem, fused deg =====================
// Per tile, per thread: A chunks idx = tid + i*256 (i<4): row idx>>3, chunk idx&7.
//                       B chunks idx = tid + i*256 (i<2): row idx>>3, chunk idx&7.
#define LDG_TILE(bA, bB, t_) do {                                                  \
    int k0 = (t_) * BK2;                                                           \
    _Pragma("unroll")                                                              \
    for (int i_ = 0; i_ < 4; ++i_) {                                               \
        int idx = tid + i_ * 256;                                                  \
        bA[i_] = *(const float4*)(Abase + (size_t)(idx >> 3) * NN + k0 + (idx & 7) * 4); \
    }                                                                              \
    _Pragma("unroll")                                                              \
    for (int i_ = 0; i_ < 2; ++i_) {                                               \
        int idx = tid + i_ * 256;                                                  \
        bB[i_] = *(const float4*)(Bbase + (size_t)(idx >> 3) * NN + k0 + (idx & 7) * 4); \
    }                                                                              \
} while (0)

#define STS_TILE(bA, bB, st) do {                                                  \
    uint32_t* base = sm + (st) * STG_WORDS;                                        \
    _Pragma("unroll")                                                              \
    for (int i_ = 0; i_ < 4; ++i_) {                                               \
        float4 v = bA[i_];                                                         \
        int idx = tid + i_ * 256;                                                  \
        dsum[i_] += (v.x + v.y) + (v.z + v.w);                                     \
        uint32_t lo, hi;                                                           \
        CVT2(lo, v.y, v.x); CVT2(hi, v.w, v.z);                                    \
        base[(idx >> 3) * AW + (idx & 7) * 2]     = lo;                            \
        base[(idx >> 3) * AW + (idx & 7) * 2 + 1] = hi;                            \
    }                                                                              \
    _Pragma("unroll")                                                              \
    for (int i_ = 0; i_ < 2; ++i_) {                                               \
        float4 v = bB[i_];                                                         \
        int idx = tid + i_ * 256;                                                  \
        uint32_t lo, hi;                                                           \
        CVT2(lo, v.y, v.x); CVT2(hi, v.w, v.z);                                    \
        base[A_WORDS + (idx >> 3) * AW + (idx & 7) * 2]     = lo;                  \
        base[A_WORDS + (idx >> 3) * AW + (idx & 7) * 2 + 1] = hi;                  \
    }                                                                              \
} while (0)

#define MMA_STAGE(st) do {                                                         \
    const uint32_t* As = sm + (st) * STG_WORDS;                                    \
    const uint32_t* Bs = As + A_WORDS;                                             \
    _Pragma("unroll")                                                              \
    for (int s_ = 0; s_ < 2; ++s_) {                                               \
        uint32_t a0 = As[(m0 + grp)     * AW + s_ * 8 + kq];                       \
        uint32_t a1 = As[(m0 + grp + 8) * AW + s_ * 8 + kq];                       \
        uint32_t a2 = As[(m0 + grp)     * AW + s_ * 8 + 4 + kq];                   \
        uint32_t a3 = As[(m0 + grp + 8) * AW + s_ * 8 + 4 + kq];                   \
        _Pragma("unroll")                                                          \
        for (int t_ = 0; t_ < 8; ++t_) {                                           \
            uint32_t b0 = Bs[(t_ * 8 + grp) * AW + s_ * 8 + kq];                   \
            uint32_t b1 = Bs[(t_ * 8 + grp) * AW + s_ * 8 + 4 + kq];               \
            mma_bf16(acc[t_], a0, a1, a2, a3, b0, b1);                             \
        }                                                                          \
    }                                                                              \
} while (0)

#define BODY(i_, BUFX_A, BUFX_B, BUFY_A, BUFY_B) do {                              \
    if ((i_) + 2 < NT) LDG_TILE(BUFX_A, BUFX_B, (i_) + 2);                         \
    __syncthreads();                                                               \
    MMA_STAGE((i_) % 3);                                                           \
    if ((i_) + 1 < NT) STS_TILE(BUFY_A, BUFY_B, ((i_) + 1) % 3);                   \
} while (0)

__global__ __launch_bounds__(256, 2) void sage_mma_kernel(const float* __restrict__ A) {
    extern __shared__ uint32_t sm[];
    const int tid  = threadIdx.x;
    const int wid  = tid >> 5;
    const int lane = tid & 31;
    const int grp  = lane >> 2;       // 0..7
    const int kq   = lane & 3;        // 0..3
    const int m0   = wid * 16;        // 8 warps x m16

    const int mtile = blockIdx.x >> 2;       // 0..63
    const int kh    = blockIdx.x & 3;        // 0..3
    const float* Abase = A + (size_t)mtile * BM * NN + (size_t)kh * KHALF;
    const float* Bbase = g_YT + (size_t)kh * KHALF;

    float acc[8][4];
#pragma unroll
    for (int t = 0; t < 8; ++t)
#pragma unroll
        for (int r = 0; r < 4; ++r) acc[t][r] = 0.0f;
    float dsum[4] = {0.f, 0.f, 0.f, 0.f};

    float4 buf1A[4], buf1B[2], buf2A[4], buf2B[2];

    // prolog: tile0 -> stage0 (via buf1), tile1 -> buf2
    LDG_TILE(buf1A, buf1B, 0);
    STS_TILE(buf1A, buf1B, 0);
    LDG_TILE(buf2A, buf2B, 1);

    for (int i = 0; i < NT; i += 2) {
        BODY(i,     buf1A, buf1B, buf2A, buf2B);   // ldg->buf1, sts buf2
        BODY(i + 1, buf2A, buf2B, buf1A, buf1B);   // ldg->buf2, sts buf1
    }

    // deg partials: thread owns rows (tid>>3)+32*i, 8 chunk-threads per row (lane&7)
#pragma unroll
    for (int i = 0; i < 4; ++i) {
        float d = dsum[i];
        d += __shfl_down_sync(0xFFFFFFFFu, d, 4);
        d += __shfl_down_sync(0xFFFFFFFFu, d, 2);
        d += __shfl_down_sync(0xFFFFFFFFu, d, 1);
        if ((lane & 7) == 0)
            g_degp[kh][mtile * BM + (tid >> 3) + i * 32] = d;
    }

    // store partial T (64 cols)
    float* dst = g_T[kh];
    int row_lo = mtile * BM + m0 + grp;
    int row_hi = row_lo + 8;
#pragma unroll
    for (int t = 0; t < 8; ++t) {
        int col = t * 8 + 2 * kq;
        *(float2*)&dst[(size_t)row_lo * OO + col] = make_float2(acc[t][0], acc[t][1]);
        *(float2*)&dst[(size_t)row_hi * OO + col] = make_float2(acc[t][2], acc[t][3]);
    }
}

// ===================== kernel 3: combine + epilogue =====================
__global__ __launch_bounds__(256) void epilogue_kernel(float* __restrict__ out) {
    int idx = blockIdx.x * blockDim.x + threadIdx.x;   // r*64 + c
    int r = idx >> 6;
    float deg = 1.0f, t = 0.0f;
#pragma unroll
    for (int s = 0; s < SPLITK; ++s) {
        deg += g_degp[s][r];
        t   += g_T[s][idx];
    }
    out[idx] = g_XW1[idx] + t / deg;
}

// -------------------- launch --------------------
extern "C" void kernel_launch(void* const* d_in, const int* in_sizes, int n_in,
                              void* d_out, int out_size) {
    const float* adj      = (const float*)d_in[0];  // [8192, 8192]
    const float* features = (const float*)d_in[1];  // [8192, 64]
    const float* W        = (const float*)d_in[2];  // [64, 128]
    float* out            = (float*)d_out;          // [8192, 64]

    cudaFuncSetAttribute(proj_kernel,
                         cudaFuncAttributeMaxDynamicSharedMemorySize, PROJ_SMEM);
    cudaFuncSetAttribute(sage_mma_kernel,
                         cudaFuncAttributeMaxDynamicSharedMemorySize, SMEM_MAIN);

    proj_kernel<<<NN / 32, 256, PROJ_SMEM>>>(features, W);
    sage_mma_kernel<<<SPLITK * (NN / BM), 256, SMEM_MAIN>>>(adj);
    epilogue_kernel<<<(NN * OO) / 256, 256>>>(out);
}